// round 1
// baseline (speedup 1.0000x reference)
#include <cuda_runtime.h>

// ---------------- constants ----------------
constexpr int F = 114176;  // per-example scaled-gradient feature length
constexpr int OW0 = 0, OB0 = 1728, OW1 = 1792, OB1 = 38656, OW2 = 38720,
              OB2 = 75584, OW3 = 75648, OB3 = 112512, OFC = 112576;

// ---------------- scratch (device globals; no allocation allowed) ----------
__device__ float g_x  [128*3*84*84];
__device__ float g_r0 [128*64*84*84];
__device__ float g_d0 [128*64*84*84];
__device__ float g_p0 [128*64*42*42];
__device__ float g_r1 [128*64*42*42];
__device__ float g_d1 [128*64*42*42];
__device__ float g_dp0[128*64*42*42];
__device__ unsigned char g_i0[128*64*42*42];
__device__ float g_p1 [128*64*21*21];
__device__ float g_r2 [128*64*21*21];
__device__ float g_d2 [128*64*21*21];
__device__ float g_dp1[128*64*21*21];
__device__ unsigned char g_i1[128*64*21*21];
__device__ float g_p2 [128*64*10*10];
__device__ float g_r3 [128*64*10*10];
__device__ float g_d3 [128*64*10*10];
__device__ float g_dp2[128*64*10*10];
__device__ unsigned char g_i2[128*64*10*10];
__device__ float g_p3 [128*64*5*5];
__device__ unsigned char g_i3[128*64*5*5];
__device__ float g_wt [64*64*9];
__device__ float g_G  [128*(size_t)F];
__device__ float g_part[8*4096];

// ---------------- kernels ----------------
__global__ void pack_x_k(const float* __restrict__ x1, const float* __restrict__ x2,
                         float* __restrict__ xo) {
    int t = blockIdx.x*256 + threadIdx.x;
    const int P = 3*84*84;
    if (t >= 128*P) return;
    int n = t / P, k = t - n*P;
    xo[t] = (n < 64) ? x1[n*P + k] : x2[(n-64)*P + k];
}

// direct 3x3 SAME conv, OC=64, each thread: 2 oc x 4 px strip
template<int IC, bool RELU>
__launch_bounds__(128)
__global__ void conv_k(const float* __restrict__ in, const float* __restrict__ w,
                       const float* __restrict__ bias, float* __restrict__ out,
                       int H, int W)
{
    const int n = blockIdx.z;
    const int oc0 = blockIdx.y * 2;
    const int WS = (W + 3) >> 2;
    __shared__ float ws[2*IC*9];
    __shared__ float bs[2];
    for (int i = threadIdx.x; i < 2*IC*9; i += 128)
        ws[i] = w[oc0*IC*9 + i];
    if (threadIdx.x < 2) bs[threadIdx.x] = bias ? bias[oc0 + threadIdx.x] : 0.0f;
    __syncthreads();
    int s = blockIdx.x*128 + threadIdx.x;
    if (s >= H*WS) return;
    int y = s / WS, x0 = (s - y*WS) * 4;
    float acc0[4], acc1[4];
    #pragma unroll
    for (int p = 0; p < 4; p++) { acc0[p] = bs[0]; acc1[p] = bs[1]; }
    const float* ip = in + (size_t)n*IC*H*W;
    #pragma unroll 1
    for (int ic = 0; ic < IC; ic++, ip += H*W) {
        float v[3][6];
        #pragma unroll
        for (int u = 0; u < 3; u++) {
            int yy = y - 1 + u;
            bool rv = (unsigned)yy < (unsigned)H;
            const float* rp = ip + yy*W;
            #pragma unroll
            for (int j = 0; j < 6; j++) {
                int xx = x0 - 1 + j;
                v[u][j] = (rv && (unsigned)xx < (unsigned)W) ? rp[xx] : 0.0f;
            }
        }
        const float* wp0 = ws + ic*9;
        const float* wp1 = ws + (IC + ic)*9;
        #pragma unroll
        for (int u = 0; u < 3; u++)
        #pragma unroll
        for (int dv = 0; dv < 3; dv++) {
            float w0v = wp0[u*3+dv], w1v = wp1[u*3+dv];
            #pragma unroll
            for (int p = 0; p < 4; p++) {
                acc0[p] += w0v * v[u][p+dv];
                acc1[p] += w1v * v[u][p+dv];
            }
        }
    }
    float* op0 = out + ((size_t)(n*64 + oc0)*H + y)*W;
    float* op1 = op0 + (size_t)H*W;
    #pragma unroll
    for (int p = 0; p < 4; p++) {
        int x = x0 + p;
        if (x < W) {
            float a0 = acc0[p], a1 = acc1[p];
            if (RELU) { a0 = a0 > 0.f ? a0 : 0.f; a1 = a1 > 0.f ? a1 : 0.f; }
            op0[x] = a0; op1[x] = a1;
        }
    }
}

__global__ void pool_k(const float* __restrict__ r, float* __restrict__ p,
                       unsigned char* __restrict__ idx, int H, int W, int Hp, int Wp)
{
    int t = blockIdx.x*256 + threadIdx.x;
    int tot = 128*64*Hp*Wp;
    if (t >= tot) return;
    int px = t % Wp, py = (t / Wp) % Hp, ncc = t / (Wp*Hp);
    const float* base = r + ((size_t)ncc*H + 2*py)*W + 2*px;
    float v0 = base[0], v1 = base[1], v2 = base[W], v3 = base[W+1];
    float m = v0; int i = 0;
    if (v1 > m) { m = v1; i = 1; }
    if (v2 > m) { m = v2; i = 2; }
    if (v3 > m) { m = v3; i = 3; }
    p[t] = m; idx[t] = (unsigned char)i;
}

// delta[cell] = (cell is argmax of its window) && (relu active) ? dp[pool cell] : 0
__global__ void unpool_k(const float* __restrict__ dp, const unsigned char* __restrict__ idx,
                         const float* __restrict__ r, float* __restrict__ delta,
                         int H, int W, int Hp, int Wp)
{
    int t = blockIdx.x*256 + threadIdx.x;
    int tot = 128*64*H*W;
    if (t >= tot) return;
    int x = t % W, y = (t / W) % H, ncc = t / (W*H);
    float val = 0.0f;
    if (y < 2*Hp && x < 2*Wp) {
        int py = y >> 1, px = x >> 1, j = ((y & 1) << 1) | (x & 1);
        int pi = (ncc*Hp + py)*Wp + px;
        if (idx[pi] == j && r[t] > 0.0f) val = dp[pi];
    }
    delta[t] = val;
}

// backward seed: d p3 = fc_w[c] (same for all examples), unpool through pool3+relu3
__global__ void unpool_fc_k(const float* __restrict__ fcw, const int* __restrict__ cptr,
                            const unsigned char* __restrict__ idx, const float* __restrict__ r,
                            float* __restrict__ delta)
{
    int t = blockIdx.x*256 + threadIdx.x;
    if (t >= 128*64*100) return;
    int x = t % 10, y = (t / 10) % 10, ch = (t / 100) % 64, n = t / 6400;
    int py = y >> 1, px = x >> 1, j = ((y & 1) << 1) | (x & 1);
    int pi = ((n*64 + ch)*5 + py)*5 + px;
    float val = 0.0f;
    if (idx[pi] == j && r[t] > 0.0f) {
        int cc = cptr[0];
        val = fcw[cc*1600 + ch*25 + py*5 + px];
    }
    delta[t] = val;
}

// wT[ic,oc,u,v] = w[oc,ic,2-u,2-v]  -> backward-data conv == forward conv with wT
__global__ void transw_k(const float* __restrict__ w, float* __restrict__ wt) {
    int t = blockIdx.x*256 + threadIdx.x;
    if (t >= 64*64*9) return;
    int uv = t % 9, ic = (t / 9) % 64, oc = t / 576;
    int u = uv / 3, v = uv % 3;
    wt[(ic*64 + oc)*9 + (2-u)*3 + (2-v)] = w[t];
}

// per-example weight gradient: gw[oc,ic,u,v] = sum_{y,x} delta[oc,y,x]*in[ic,y+u-1,x+v-1]
// block = (oc, n); delta plane + ICC padded input planes in smem; sliding 3x3 window
template<int IC, int ICC, int RG>
__global__ void wgrad_k(const float* __restrict__ delta, const float* __restrict__ in,
                        float* __restrict__ G, int gofs, const float* __restrict__ scal,
                        int sidx, int H, int W)
{
    const int n = blockIdx.y, oc = blockIdx.x;
    extern __shared__ float sm[];
    float* ds = sm;                         // H*W
    const int PH = H + 2, PW = W + 2;
    float* ins = sm + H*W;                  // ICC*PH*PW
    float* red = ins + ICC*PH*PW;           // ICC*9*RG
    const int tid = threadIdx.x;
    const int icl = tid / RG, rg = tid - icl*RG;
    const int NT = ICC*RG;
    const float* dpp = delta + (size_t)(n*64 + oc)*H*W;
    for (int i = tid; i < H*W; i += NT) ds[i] = dpp[i];
    const float s = scal[sidx];
    for (int chunk = 0; chunk < IC; chunk += ICC) {
        __syncthreads();
        for (int i = tid; i < ICC*PH*PW; i += NT) {
            int icp = i / (PH*PW); int r2 = i - icp*(PH*PW);
            int yy = r2 / PW - 1; int xx = r2 - (yy + 1)*PW - 1;
            float val = 0.0f;
            if ((unsigned)yy < (unsigned)H && (unsigned)xx < (unsigned)W)
                val = in[(size_t)(n*IC + chunk + icp)*H*W + yy*W + xx];
            ins[i] = val;
        }
        __syncthreads();
        float acc[9];
        #pragma unroll
        for (int k = 0; k < 9; k++) acc[k] = 0.0f;
        const float* myin = ins + icl*PH*PW;
        for (int y = rg; y < H; y += RG) {
            const float* r0p = myin + y*PW;
            const float* r1p = r0p + PW;
            const float* r2p = r1p + PW;
            const float* drow = ds + y*W;
            float a0 = r0p[0], a1 = r0p[1];
            float b0 = r1p[0], b1 = r1p[1];
            float c0 = r2p[0], c1 = r2p[1];
            #pragma unroll 3
            for (int x = 0; x < W; x++) {
                float a2 = r0p[x+2], b2 = r1p[x+2], c2 = r2p[x+2];
                float d = drow[x];
                acc[0] += d*a0; acc[1] += d*a1; acc[2] += d*a2;
                acc[3] += d*b0; acc[4] += d*b1; acc[5] += d*b2;
                acc[6] += d*c0; acc[7] += d*c1; acc[8] += d*c2;
                a0 = a1; a1 = a2; b0 = b1; b1 = b2; c0 = c1; c1 = c2;
            }
        }
        #pragma unroll
        for (int k = 0; k < 9; k++) red[(icl*9 + k)*RG + rg] = acc[k];
        __syncthreads();
        for (int o = tid; o < ICC*9; o += NT) {
            float t2 = 0.0f;
            for (int r = 0; r < RG; r++) t2 += red[o*RG + r];
            int icg = chunk + o / 9, uv = o - (o / 9)*9;
            G[(size_t)n*F + gofs + (oc*IC + icg)*9 + uv] = s * t2;
        }
    }
}

__global__ void bgrad_k(const float* __restrict__ delta, float* __restrict__ G,
                        int gofs, const float* __restrict__ scal, int sidx, int HW)
{
    const int n = blockIdx.y, oc = blockIdx.x;
    const float* dp = delta + (size_t)(n*64 + oc)*HW;
    __shared__ float sm[128];
    float a = 0.0f;
    for (int i = threadIdx.x; i < HW; i += 128) a += dp[i];
    sm[threadIdx.x] = a; __syncthreads();
    for (int st = 64; st > 0; st >>= 1) {
        if (threadIdx.x < st) sm[threadIdx.x] += sm[threadIdx.x + st];
        __syncthreads();
    }
    if (threadIdx.x == 0) G[(size_t)n*F + gofs + oc] = scal[sidx]*sm[0];
}

// fc_w gradient row c == p3 feature; scaled copy into G
__global__ void copyp3_k(const float* __restrict__ p3, float* __restrict__ G,
                         const float* __restrict__ scal)
{
    int t = blockIdx.x*256 + threadIdx.x;
    if (t >= 128*1600) return;
    int n = t / 1600, j = t - n*1600;
    G[(size_t)n*F + OFC + j] = scal[8]*p3[t];
}

// K partials: split-K over F into 8 slices, 16x16 output tiles
__global__ void gemm_part_k(const float* __restrict__ G, float* __restrict__ part)
{
    const int ty = threadIdx.y, tx = threadIdx.x;
    const int bn = blockIdx.y*16, bm = blockIdx.x*16, sp = blockIdx.z;
    __shared__ float A[16][65], B[16][65];
    const int f0 = sp*(F/8);
    const int tid = ty*16 + tx, row = tid >> 4, q = tid & 15;
    float acc = 0.0f;
    for (int f = f0; f < f0 + F/8; f += 64) {
        float4 a4 = *(const float4*)(G + (size_t)(bn + row)*F + f + q*4);
        float4 b4 = *(const float4*)(G + (size_t)(64 + bm + row)*F + f + q*4);
        A[row][q*4+0] = a4.x; A[row][q*4+1] = a4.y; A[row][q*4+2] = a4.z; A[row][q*4+3] = a4.w;
        B[row][q*4+0] = b4.x; B[row][q*4+1] = b4.y; B[row][q*4+2] = b4.z; B[row][q*4+3] = b4.w;
        __syncthreads();
        #pragma unroll
        for (int k = 0; k < 64; k++) acc += A[ty][k]*B[tx][k];
        __syncthreads();
    }
    part[sp*4096 + (bn + ty)*64 + (bm + tx)] = acc;
}

__global__ void reduce_k(const float* __restrict__ part, const float* __restrict__ scal,
                         float* __restrict__ out)
{
    int t = blockIdx.x*256 + threadIdx.x;
    if (t >= 4096) return;
    float a = scal[9]*scal[9];   // fc_b contribution: <e_c, e_c> * s^2
    #pragma unroll
    for (int sp = 0; sp < 8; sp++) a += part[sp*4096 + t];
    out[t] = a;
}

// ---------------- host ----------------
extern "C" void kernel_launch(void* const* d_in, const int* in_sizes, int n_in,
                              void* d_out, int out_size)
{
    const float* x1  = (const float*)d_in[0];
    const float* x2  = (const float*)d_in[1];
    const float* scal= (const float*)d_in[2];
    const int*   cp  = (const int*)  d_in[3];
    const float* w0  = (const float*)d_in[4];
    const float* b0  = (const float*)d_in[5];
    const float* w1  = (const float*)d_in[6];
    const float* b1  = (const float*)d_in[7];
    const float* w2  = (const float*)d_in[8];
    const float* b2  = (const float*)d_in[9];
    const float* w3  = (const float*)d_in[10];
    const float* b3  = (const float*)d_in[11];
    const float* fcw = (const float*)d_in[12];
    float* out = (float*)d_out;

    float *xp,*r0,*d0,*p0,*r1,*d1,*dp0,*p1,*r2,*d2,*dp1,*p2,*r3,*d3,*dp2,*p3,*wt,*G,*part;
    unsigned char *i0,*i1,*i2,*i3;
    cudaGetSymbolAddress((void**)&xp,  g_x);
    cudaGetSymbolAddress((void**)&r0,  g_r0);
    cudaGetSymbolAddress((void**)&d0,  g_d0);
    cudaGetSymbolAddress((void**)&p0,  g_p0);
    cudaGetSymbolAddress((void**)&r1,  g_r1);
    cudaGetSymbolAddress((void**)&d1,  g_d1);
    cudaGetSymbolAddress((void**)&dp0, g_dp0);
    cudaGetSymbolAddress((void**)&i0,  g_i0);
    cudaGetSymbolAddress((void**)&p1,  g_p1);
    cudaGetSymbolAddress((void**)&r2,  g_r2);
    cudaGetSymbolAddress((void**)&d2,  g_d2);
    cudaGetSymbolAddress((void**)&dp1, g_dp1);
    cudaGetSymbolAddress((void**)&i1,  g_i1);
    cudaGetSymbolAddress((void**)&p2,  g_p2);
    cudaGetSymbolAddress((void**)&r3,  g_r3);
    cudaGetSymbolAddress((void**)&d3,  g_d3);
    cudaGetSymbolAddress((void**)&dp2, g_dp2);
    cudaGetSymbolAddress((void**)&i2,  g_i2);
    cudaGetSymbolAddress((void**)&p3,  g_p3);
    cudaGetSymbolAddress((void**)&i3,  g_i3);
    cudaGetSymbolAddress((void**)&wt,  g_wt);
    cudaGetSymbolAddress((void**)&G,   g_G);
    cudaGetSymbolAddress((void**)&part,g_part);

    const int smem0  = (84*84 + 3*86*86 + 3*9*84)*4;   // 126048
    const int smem42 = (42*42 + 8*44*44 + 8*9*32)*4;   // 78224
    const int smem21 = (21*21 + 8*23*23 + 8*9*32)*4;   // 27908
    const int smem10 = (10*10 + 8*12*12 + 8*9*32)*4;   // 14224
    cudaFuncSetAttribute(wgrad_k<3,3,84>,  cudaFuncAttributeMaxDynamicSharedMemorySize, smem0);
    cudaFuncSetAttribute(wgrad_k<64,8,32>, cudaFuncAttributeMaxDynamicSharedMemorySize, smem42);

    // ---- forward ----
    pack_x_k<<<(128*3*84*84 + 255)/256, 256>>>(x1, x2, xp);
    conv_k<3,true><<<dim3(14,32,128),128>>>(xp, w0, b0, r0, 84, 84);
    pool_k<<<(128*64*42*42 + 255)/256, 256>>>(r0, p0, i0, 84, 84, 42, 42);
    conv_k<64,true><<<dim3(4,32,128),128>>>(p0, w1, b1, r1, 42, 42);
    pool_k<<<(128*64*21*21 + 255)/256, 256>>>(r1, p1, i1, 42, 42, 21, 21);
    conv_k<64,true><<<dim3(1,32,128),128>>>(p1, w2, b2, r2, 21, 21);
    pool_k<<<(128*64*10*10 + 255)/256, 256>>>(r2, p2, i2, 21, 21, 10, 10);
    conv_k<64,true><<<dim3(1,32,128),128>>>(p2, w3, b3, r3, 10, 10);
    pool_k<<<(128*64*5*5 + 255)/256, 256>>>(r3, p3, i3, 10, 10, 5, 5);

    // ---- backward (scalar output c) ----
    unpool_fc_k<<<(128*64*100 + 255)/256, 256>>>(fcw, cp, i3, r3, d3);
    transw_k<<<144,256>>>(w3, wt);
    conv_k<64,false><<<dim3(1,32,128),128>>>(d3, wt, nullptr, dp2, 10, 10);
    unpool_k<<<(128*64*21*21 + 255)/256, 256>>>(dp2, i2, r2, d2, 21, 21, 10, 10);
    transw_k<<<144,256>>>(w2, wt);
    conv_k<64,false><<<dim3(1,32,128),128>>>(d2, wt, nullptr, dp1, 21, 21);
    unpool_k<<<(128*64*42*42 + 255)/256, 256>>>(dp1, i1, r1, d1, 42, 42, 21, 21);
    transw_k<<<144,256>>>(w1, wt);
    conv_k<64,false><<<dim3(4,32,128),128>>>(d1, wt, nullptr, dp0, 42, 42);
    unpool_k<<<(128*64*84*84 + 255)/256, 256>>>(dp0, i0, r0, d0, 84, 84, 42, 42);

    // ---- per-example gradients -> scaled feature matrix G ----
    wgrad_k<3,3,84> <<<dim3(64,128), 252, smem0 >>>(d0, xp, G, OW0, scal, 0, 84, 84);
    bgrad_k         <<<dim3(64,128), 128       >>>(d0, G, OB0, scal, 1, 84*84);
    wgrad_k<64,8,32><<<dim3(64,128), 256, smem42>>>(d1, p0, G, OW1, scal, 2, 42, 42);
    bgrad_k         <<<dim3(64,128), 128       >>>(d1, G, OB1, scal, 3, 42*42);
    wgrad_k<64,8,32><<<dim3(64,128), 256, smem21>>>(d2, p1, G, OW2, scal, 4, 21, 21);
    bgrad_k         <<<dim3(64,128), 128       >>>(d2, G, OB2, scal, 5, 21*21);
    wgrad_k<64,8,32><<<dim3(64,128), 256, smem10>>>(d3, p2, G, OW3, scal, 6, 10, 10);
    bgrad_k         <<<dim3(64,128), 128       >>>(d3, G, OB3, scal, 7, 10*10);
    copyp3_k<<<(128*1600 + 255)/256, 256>>>(p3, G, scal);

    // ---- K = G1 G2^T + s_fcb^2 ----
    gemm_part_k<<<dim3(4,4,8), dim3(16,16)>>>(G, part);
    reduce_k<<<16,256>>>(part, scal, out);
}

// round 2
// speedup vs baseline: 1.9791x; 1.9791x over previous
#include <cuda_runtime.h>

// ---------------- constants ----------------
constexpr int F = 114176;  // per-example scaled-gradient feature length
constexpr int OW0 = 0, OB0 = 1728, OW1 = 1792, OB1 = 38656, OW2 = 38720,
              OB2 = 75584, OW3 = 75648, OB3 = 112512, OFC = 112576;

// ---------------- scratch (device globals) ----------------
__device__ float g_x  [128*3*84*84];
__device__ float g_d0 [128*64*84*84];
__device__ float g_p0 [128*64*42*42];
__device__ float g_d1 [128*64*42*42];
__device__ float g_dp0[128*64*42*42];
__device__ unsigned char g_i0[128*64*42*42];
__device__ float g_p1 [128*64*21*21];
__device__ float g_d2 [128*64*21*21];
__device__ float g_dp1[128*64*21*21];
__device__ unsigned char g_i1[128*64*21*21];
__device__ float g_p2 [128*64*10*10];
__device__ float g_d3 [128*64*10*10];
__device__ float g_dp2[128*64*10*10];
__device__ unsigned char g_i2[128*64*10*10];
__device__ float g_p3 [128*64*5*5];
__device__ unsigned char g_i3[128*64*5*5];
__device__ float g_wt [64*64*9];
__device__ float g_G  [128*(size_t)F];
__device__ float g_part[8*4096];

// ---------------- kernels ----------------
__global__ void pack_x_k(const float* __restrict__ x1, const float* __restrict__ x2,
                         float* __restrict__ xo) {
    int t = blockIdx.x*256 + threadIdx.x;
    const int P = 3*84*84;
    if (t >= 128*P) return;
    int n = t / P, k = t - n*P;
    xo[t] = (n < 64) ? x1[n*P + k] : x2[(n-64)*P + k];
}

// fused conv3x3(SAME) + bias + relu + 2x2 maxpool(VALID).
// thread = one pooled cell (2x2 conv px) x 8 oc. idx in 0..3, or 4 if max<=0.
template<int IC>
__launch_bounds__(128)
__global__ void convpool_k(const float* __restrict__ in, const float* __restrict__ w,
                           const float* __restrict__ bias, float* __restrict__ p,
                           unsigned char* __restrict__ idx,
                           int H, int W, int Hp, int Wp)
{
    const int n = blockIdx.z, oc0 = blockIdx.y*8;
    __shared__ float ws[8*IC*12];
    __shared__ float bs[8];
    for (int i = threadIdx.x; i < 8*IC*9; i += 128) {
        int oi = i/9, k = i - oi*9;
        ws[oi*12+k] = w[(size_t)oc0*IC*9 + i];
    }
    if (threadIdx.x < 8) bs[threadIdx.x] = bias[oc0+threadIdx.x];
    __syncthreads();
    int t = blockIdx.x*128 + threadIdx.x;
    if (t >= Hp*Wp) return;
    int py = t / Wp, px = t - py*Wp;
    int y0 = py*2, x0 = px*2;
    int offs[4][4];
    #pragma unroll
    for (int u = 0; u < 4; u++) {
        int yy = y0-1+u; bool rv = (unsigned)yy < (unsigned)H;
        #pragma unroll
        for (int j = 0; j < 4; j++) {
            int xx = x0-1+j;
            offs[u][j] = (rv && (unsigned)xx < (unsigned)W) ? yy*W+xx : -1;
        }
    }
    float acc[8][4];
    #pragma unroll
    for (int o = 0; o < 8; o++) {
        float b = bs[o];
        acc[o][0]=b; acc[o][1]=b; acc[o][2]=b; acc[o][3]=b;
    }
    const float* ip = in + (size_t)n*IC*H*W;
    #pragma unroll 1
    for (int ic = 0; ic < IC; ic++, ip += H*W) {
        float v[4][4];
        #pragma unroll
        for (int u = 0; u < 4; u++)
        #pragma unroll
        for (int j = 0; j < 4; j++)
            v[u][j] = (offs[u][j] >= 0) ? ip[offs[u][j]] : 0.0f;
        #pragma unroll
        for (int o = 0; o < 8; o++) {
            float wr[12];
            *(float4*)&wr[0] = *(const float4*)&ws[(o*IC+ic)*12];
            *(float4*)&wr[4] = *(const float4*)&ws[(o*IC+ic)*12+4];
            wr[8] = ws[(o*IC+ic)*12+8];
            #pragma unroll
            for (int u = 0; u < 3; u++)
            #pragma unroll
            for (int vv = 0; vv < 3; vv++) {
                float wv = wr[u*3+vv];
                acc[o][0] += wv*v[u  ][vv  ];
                acc[o][1] += wv*v[u  ][vv+1];
                acc[o][2] += wv*v[u+1][vv  ];
                acc[o][3] += wv*v[u+1][vv+1];
            }
        }
    }
    #pragma unroll
    for (int o = 0; o < 8; o++) {
        float a0 = fmaxf(acc[o][0],0.f), a1 = fmaxf(acc[o][1],0.f),
              a2 = fmaxf(acc[o][2],0.f), a3 = fmaxf(acc[o][3],0.f);
        float m = a0; int am = 0;
        if (a1 > m) { m = a1; am = 1; }
        if (a2 > m) { m = a2; am = 2; }
        if (a3 > m) { m = a3; am = 3; }
        size_t ob = ((size_t)(n*64+oc0+o)*Hp + py)*Wp + px;
        p[ob] = m;
        idx[ob] = (m > 0.f) ? (unsigned char)am : (unsigned char)4;
    }
}

// plain conv3x3 SAME (backward-data), 2x2 px x 8 oc tiles, no bias/relu
template<int IC>
__launch_bounds__(128)
__global__ void conv2_k(const float* __restrict__ in, const float* __restrict__ w,
                        float* __restrict__ out, int H, int W)
{
    const int n = blockIdx.z, oc0 = blockIdx.y*8;
    const int TW = (W+1) >> 1, TH = (H+1) >> 1;
    __shared__ float ws[8*IC*12];
    for (int i = threadIdx.x; i < 8*IC*9; i += 128) {
        int oi = i/9, k = i - oi*9;
        ws[oi*12+k] = w[(size_t)oc0*IC*9 + i];
    }
    __syncthreads();
    int t = blockIdx.x*128 + threadIdx.x;
    if (t >= TH*TW) return;
    int ty = t / TW, tx = t - ty*TW;
    int y0 = ty*2, x0 = tx*2;
    int offs[4][4];
    #pragma unroll
    for (int u = 0; u < 4; u++) {
        int yy = y0-1+u; bool rv = (unsigned)yy < (unsigned)H;
        #pragma unroll
        for (int j = 0; j < 4; j++) {
            int xx = x0-1+j;
            offs[u][j] = (rv && (unsigned)xx < (unsigned)W) ? yy*W+xx : -1;
        }
    }
    float acc[8][4];
    #pragma unroll
    for (int o = 0; o < 8; o++) { acc[o][0]=0.f; acc[o][1]=0.f; acc[o][2]=0.f; acc[o][3]=0.f; }
    const float* ip = in + (size_t)n*IC*H*W;
    #pragma unroll 1
    for (int ic = 0; ic < IC; ic++, ip += H*W) {
        float v[4][4];
        #pragma unroll
        for (int u = 0; u < 4; u++)
        #pragma unroll
        for (int j = 0; j < 4; j++)
            v[u][j] = (offs[u][j] >= 0) ? ip[offs[u][j]] : 0.0f;
        #pragma unroll
        for (int o = 0; o < 8; o++) {
            float wr[12];
            *(float4*)&wr[0] = *(const float4*)&ws[(o*IC+ic)*12];
            *(float4*)&wr[4] = *(const float4*)&ws[(o*IC+ic)*12+4];
            wr[8] = ws[(o*IC+ic)*12+8];
            #pragma unroll
            for (int u = 0; u < 3; u++)
            #pragma unroll
            for (int vv = 0; vv < 3; vv++) {
                float wv = wr[u*3+vv];
                acc[o][0] += wv*v[u  ][vv  ];
                acc[o][1] += wv*v[u  ][vv+1];
                acc[o][2] += wv*v[u+1][vv  ];
                acc[o][3] += wv*v[u+1][vv+1];
            }
        }
    }
    bool xv = (x0+1 < W), yv = (y0+1 < H);
    #pragma unroll
    for (int o = 0; o < 8; o++) {
        float* op = out + ((size_t)(n*64+oc0+o)*H + y0)*W + x0;
        op[0] = acc[o][0];
        if (xv) op[1] = acc[o][1];
        if (yv) { op[W] = acc[o][2]; if (xv) op[W+1] = acc[o][3]; }
    }
}

// unpool using only (dp, idx); idx==4 means relu-inactive window
__global__ void unpool2_k(const float* __restrict__ dp, const unsigned char* __restrict__ idx,
                          float* __restrict__ delta, int H, int W, int Hp, int Wp)
{
    int t = blockIdx.x*256 + threadIdx.x;
    int tot = 128*64*H*W;
    if (t >= tot) return;
    int x = t % W, y = (t / W) % H, ncc = t / (W*H);
    float val = 0.0f;
    if (y < 2*Hp && x < 2*Wp) {
        int py = y >> 1, px = x >> 1, j = ((y & 1) << 1) | (x & 1);
        int pi = (ncc*Hp + py)*Wp + px;
        if (idx[pi] == j) val = dp[pi];
    }
    delta[t] = val;
}

// backward seed through pool3+relu3
__global__ void unpool_fc_k(const float* __restrict__ fcw, const int* __restrict__ cptr,
                            const unsigned char* __restrict__ idx, float* __restrict__ delta)
{
    int t = blockIdx.x*256 + threadIdx.x;
    if (t >= 128*64*100) return;
    int x = t % 10, y = (t / 10) % 10, ch = (t / 100) % 64, n = t / 6400;
    int py = y >> 1, px = x >> 1, j = ((y & 1) << 1) | (x & 1);
    int pi = ((n*64 + ch)*5 + py)*5 + px;
    float val = 0.0f;
    if (idx[pi] == j) {
        int cc = cptr[0];
        val = fcw[cc*1600 + ch*25 + py*5 + px];
    }
    delta[t] = val;
}

__global__ void transw_k(const float* __restrict__ w, float* __restrict__ wt) {
    int t = blockIdx.x*256 + threadIdx.x;
    if (t >= 64*64*9) return;
    int uv = t % 9, ic = (t / 9) % 64, oc = t / 576;
    int u = uv / 3, v = uv % 3;
    wt[(ic*64 + oc)*9 + (2-u)*3 + (2-v)] = w[t];
}

// weight+bias gradient, layers 1..3: block = (oc group of OCC, n)
// odd smem pitches (conflict-free), warp-shuffle reductions, fused bias grad
template<int IC, int ICC, int OCC>
__global__ void wgrad2_k(const float* __restrict__ delta, const float* __restrict__ in,
                         float* __restrict__ G, int gofs, int bofs,
                         const float* __restrict__ scal, int sidx, int H, int W)
{
    const int n = blockIdx.y, oc0 = blockIdx.x*OCC;
    const int DW = W | 1;
    const int PW = (W+2) | 1;
    const int PH = H + 2;
    const int HDW = H*DW, PHW = PH*PW;
    extern __shared__ float sm[];
    float* ds   = sm;                 // OCC*HDW
    float* ins  = ds + OCC*HDW;       // ICC*PHW
    float* bred = ins + ICC*PHW;      // OCC
    const int tid = threadIdx.x;
    const int lane = tid & 31, icl = tid >> 5;
    const int NT = ICC*32;
    if (tid < OCC) bred[tid] = 0.f;
    for (int i = tid; i < OCC*HDW; i += NT) {
        int o = i / HDW, r = i - o*HDW;
        int y = r / DW, x = r - y*DW;
        ds[i] = (x < W) ? delta[(size_t)(n*64+oc0+o)*H*W + y*W + x] : 0.f;
    }
    __syncthreads();
    #pragma unroll
    for (int o = 0; o < OCC; o++) {
        float a = 0.f;
        for (int i = tid; i < HDW; i += NT) a += ds[o*HDW + i];
        #pragma unroll
        for (int off = 16; off; off >>= 1) a += __shfl_xor_sync(0xffffffffu, a, off);
        if (lane == 0) atomicAdd(&bred[o], a);
    }
    const float s  = scal[sidx];
    const float sb = scal[sidx+1];
    for (int chunk = 0; chunk < IC; chunk += ICC) {
        __syncthreads();
        for (int i = tid; i < ICC*PHW; i += NT) {
            int icp = i / PHW, r = i - icp*PHW;
            int yy = r / PW - 1, xx = r - (yy+1)*PW - 1;
            float val = 0.f;
            if ((unsigned)yy < (unsigned)H && (unsigned)xx < (unsigned)W)
                val = in[(size_t)(n*IC + chunk + icp)*H*W + yy*W + xx];
            ins[i] = val;
        }
        __syncthreads();
        float acc[OCC][9];
        #pragma unroll
        for (int o = 0; o < OCC; o++)
        #pragma unroll
        for (int k = 0; k < 9; k++) acc[o][k] = 0.f;
        const float* myin = ins + icl*PHW;
        for (int y = lane; y < H; y += 32) {
            const float* r0p = myin + y*PW;
            const float* r1p = r0p + PW;
            const float* r2p = r1p + PW;
            const float* dsy = ds + y*DW;
            float a0=r0p[0],a1=r0p[1],b0=r1p[0],b1=r1p[1],c0=r2p[0],c1=r2p[1];
            #pragma unroll 2
            for (int x = 0; x < W; x++) {
                float a2=r0p[x+2], b2=r1p[x+2], c2=r2p[x+2];
                #pragma unroll
                for (int o = 0; o < OCC; o++) {
                    float d = dsy[o*HDW + x];
                    acc[o][0]+=d*a0; acc[o][1]+=d*a1; acc[o][2]+=d*a2;
                    acc[o][3]+=d*b0; acc[o][4]+=d*b1; acc[o][5]+=d*b2;
                    acc[o][6]+=d*c0; acc[o][7]+=d*c1; acc[o][8]+=d*c2;
                }
                a0=a1;a1=a2;b0=b1;b1=b2;c0=c1;c1=c2;
            }
        }
        #pragma unroll
        for (int o = 0; o < OCC; o++)
        #pragma unroll
        for (int k = 0; k < 9; k++) {
            float vsum = acc[o][k];
            #pragma unroll
            for (int off = 16; off; off >>= 1)
                vsum += __shfl_xor_sync(0xffffffffu, vsum, off);
            if (lane == 0)
                G[(size_t)n*F + gofs + ((size_t)(oc0+o)*IC + chunk + icl)*9 + k] = s*vsum;
        }
    }
    __syncthreads();
    if (tid < OCC) G[(size_t)n*F + bofs + oc0 + tid] = sb*bred[tid];
}

// layer-0 weight+bias gradient (IC=3, 84x84), odd pitches, fused bias
__global__ void wgrad0_k(const float* __restrict__ delta, const float* __restrict__ in,
                         float* __restrict__ G, const float* __restrict__ scal)
{
    const int n = blockIdx.y, oc = blockIdx.x;
    extern __shared__ float sm[];
    float* ds  = sm;             // 84*85
    float* ins = ds + 84*85;     // 3*86*87
    float* red = ins + 3*86*87;  // 3*9*84
    const int tid = threadIdx.x; // 252
    const int icl = tid / 84, rg = tid - icl*84;
    for (int i = tid; i < 84*85; i += 252) {
        int y = i/85, x = i - y*85;
        ds[i] = (x < 84) ? delta[(size_t)(n*64+oc)*7056 + y*84 + x] : 0.f;
    }
    for (int i = tid; i < 3*86*87; i += 252) {
        int icp = i/(86*87), r = i - icp*(86*87);
        int yy = r/87 - 1, xx = r - (yy+1)*87 - 1;
        float val = 0.f;
        if ((unsigned)yy < 84u && (unsigned)xx < 84u)
            val = in[(size_t)(n*3+icp)*7056 + yy*84 + xx];
        ins[i] = val;
    }
    __syncthreads();
    float bp = 0.f;
    for (int i = tid; i < 84*85; i += 252) bp += ds[i];
    red[tid] = bp;
    __syncthreads();
    if (tid == 0) {
        float a = 0.f;
        for (int i = 0; i < 252; i++) a += red[i];
        G[(size_t)n*F + OB0 + oc] = scal[1]*a;
    }
    __syncthreads();
    float acc[9];
    #pragma unroll
    for (int k = 0; k < 9; k++) acc[k] = 0.f;
    {
        const float* r0p = ins + icl*86*87 + rg*87;
        const float* r1p = r0p + 87;
        const float* r2p = r1p + 87;
        const float* dsy = ds + rg*85;
        float a0=r0p[0],a1=r0p[1],b0=r1p[0],b1=r1p[1],c0=r2p[0],c1=r2p[1];
        #pragma unroll 2
        for (int x = 0; x < 84; x++) {
            float a2=r0p[x+2], b2=r1p[x+2], c2=r2p[x+2];
            float d = dsy[x];
            acc[0]+=d*a0; acc[1]+=d*a1; acc[2]+=d*a2;
            acc[3]+=d*b0; acc[4]+=d*b1; acc[5]+=d*b2;
            acc[6]+=d*c0; acc[7]+=d*c1; acc[8]+=d*c2;
            a0=a1;a1=a2;b0=b1;b1=b2;c0=c1;c1=c2;
        }
    }
    #pragma unroll
    for (int k = 0; k < 9; k++) red[(icl*9+k)*84 + rg] = acc[k];
    __syncthreads();
    const float s = scal[0];
    for (int o = tid; o < 27; o += 252) {
        float t2 = 0.f;
        for (int r = 0; r < 84; r++) t2 += red[o*84 + r];
        int icg = o/9, uv = o - icg*9;
        G[(size_t)n*F + OW0 + (oc*3 + icg)*9 + uv] = s*t2;
    }
}

// fc_w gradient row c == p3 feature; scaled copy into G
__global__ void copyp3_k(const float* __restrict__ p3, float* __restrict__ G,
                         const float* __restrict__ scal)
{
    int t = blockIdx.x*256 + threadIdx.x;
    if (t >= 128*1600) return;
    int n = t / 1600, j = t - n*1600;
    G[(size_t)n*F + OFC + j] = scal[8]*p3[t];
}

// K partials: split-K over F into 8 slices, 16x16 output tiles
__global__ void gemm_part_k(const float* __restrict__ G, float* __restrict__ part)
{
    const int ty = threadIdx.y, tx = threadIdx.x;
    const int bn = blockIdx.y*16, bm = blockIdx.x*16, sp = blockIdx.z;
    __shared__ float A[16][65], B[16][65];
    const int f0 = sp*(F/8);
    const int tid = ty*16 + tx, row = tid >> 4, q = tid & 15;
    float acc = 0.0f;
    for (int f = f0; f < f0 + F/8; f += 64) {
        float4 a4 = *(const float4*)(G + (size_t)(bn + row)*F + f + q*4);
        float4 b4 = *(const float4*)(G + (size_t)(64 + bm + row)*F + f + q*4);
        A[row][q*4+0] = a4.x; A[row][q*4+1] = a4.y; A[row][q*4+2] = a4.z; A[row][q*4+3] = a4.w;
        B[row][q*4+0] = b4.x; B[row][q*4+1] = b4.y; B[row][q*4+2] = b4.z; B[row][q*4+3] = b4.w;
        __syncthreads();
        #pragma unroll
        for (int k = 0; k < 64; k++) acc += A[ty][k]*B[tx][k];
        __syncthreads();
    }
    part[sp*4096 + (bn + ty)*64 + (bm + tx)] = acc;
}

__global__ void reduce_k(const float* __restrict__ part, const float* __restrict__ scal,
                         float* __restrict__ out)
{
    int t = blockIdx.x*256 + threadIdx.x;
    if (t >= 4096) return;
    float a = scal[9]*scal[9];
    #pragma unroll
    for (int sp = 0; sp < 8; sp++) a += part[sp*4096 + t];
    out[t] = a;
}

// ---------------- host ----------------
extern "C" void kernel_launch(void* const* d_in, const int* in_sizes, int n_in,
                              void* d_out, int out_size)
{
    const float* x1  = (const float*)d_in[0];
    const float* x2  = (const float*)d_in[1];
    const float* scal= (const float*)d_in[2];
    const int*   cp  = (const int*)  d_in[3];
    const float* w0  = (const float*)d_in[4];
    const float* b0  = (const float*)d_in[5];
    const float* w1  = (const float*)d_in[6];
    const float* b1  = (const float*)d_in[7];
    const float* w2  = (const float*)d_in[8];
    const float* b2  = (const float*)d_in[9];
    const float* w3  = (const float*)d_in[10];
    const float* b3  = (const float*)d_in[11];
    const float* fcw = (const float*)d_in[12];
    float* out = (float*)d_out;

    float *xp,*d0,*p0,*d1,*dp0,*p1,*d2,*dp1,*p2,*d3,*dp2,*p3,*wt,*G,*part;
    unsigned char *i0,*i1,*i2,*i3;
    cudaGetSymbolAddress((void**)&xp,  g_x);
    cudaGetSymbolAddress((void**)&d0,  g_d0);
    cudaGetSymbolAddress((void**)&p0,  g_p0);
    cudaGetSymbolAddress((void**)&d1,  g_d1);
    cudaGetSymbolAddress((void**)&dp0, g_dp0);
    cudaGetSymbolAddress((void**)&i0,  g_i0);
    cudaGetSymbolAddress((void**)&p1,  g_p1);
    cudaGetSymbolAddress((void**)&d2,  g_d2);
    cudaGetSymbolAddress((void**)&dp1, g_dp1);
    cudaGetSymbolAddress((void**)&i1,  g_i1);
    cudaGetSymbolAddress((void**)&p2,  g_p2);
    cudaGetSymbolAddress((void**)&d3,  g_d3);
    cudaGetSymbolAddress((void**)&dp2, g_dp2);
    cudaGetSymbolAddress((void**)&i2,  g_i2);
    cudaGetSymbolAddress((void**)&p3,  g_p3);
    cudaGetSymbolAddress((void**)&i3,  g_i3);
    cudaGetSymbolAddress((void**)&wt,  g_wt);
    cudaGetSymbolAddress((void**)&G,   g_G);
    cudaGetSymbolAddress((void**)&part,g_part);

    // dynamic smem sizes
    const int smW0 = (84*85 + 3*86*87 + 3*9*84)*4;               // 127416
    const int sm42 = (4*42*43 + 8*44*45 + 4)*4;                  // 92272
    const int sm21 = (4*21*21 + 8*23*23 + 4)*4;                  // 24000
    const int sm10 = (4*10*11 + 8*12*13 + 4)*4;                  // 6768
    cudaFuncSetAttribute(wgrad0_k, cudaFuncAttributeMaxDynamicSharedMemorySize, smW0);
    cudaFuncSetAttribute(wgrad2_k<64,8,4>, cudaFuncAttributeMaxDynamicSharedMemorySize, sm42);

    // ---- forward (conv+relu+pool fused) ----
    pack_x_k<<<(128*3*84*84 + 255)/256, 256>>>(x1, x2, xp);
    convpool_k<3> <<<dim3(14,8,128),128>>>(xp, w0, b0, p0, i0, 84, 84, 42, 42);
    convpool_k<64><<<dim3(4, 8,128),128>>>(p0, w1, b1, p1, i1, 42, 42, 21, 21);
    convpool_k<64><<<dim3(1, 8,128),128>>>(p1, w2, b2, p2, i2, 21, 21, 10, 10);
    convpool_k<64><<<dim3(1, 8,128),128>>>(p2, w3, b3, p3, i3, 10, 10, 5, 5);

    // ---- backward (scalar output c) ----
    unpool_fc_k<<<(128*64*100 + 255)/256, 256>>>(fcw, cp, i3, d3);
    transw_k<<<144,256>>>(w3, wt);
    conv2_k<64><<<dim3(1,8,128),128>>>(d3, wt, dp2, 10, 10);
    unpool2_k<<<(128*64*21*21 + 255)/256, 256>>>(dp2, i2, d2, 21, 21, 10, 10);
    transw_k<<<144,256>>>(w2, wt);
    conv2_k<64><<<dim3(1,8,128),128>>>(d2, wt, dp1, 21, 21);
    unpool2_k<<<(128*64*42*42 + 255)/256, 256>>>(dp1, i1, d1, 42, 42, 21, 21);
    transw_k<<<144,256>>>(w1, wt);
    conv2_k<64><<<dim3(4,8,128),128>>>(d1, wt, dp0, 42, 42);
    unpool2_k<<<(128*64*84*84 + 255)/256, 256>>>(dp0, i0, d0, 84, 84, 42, 42);

    // ---- per-example gradients -> scaled feature matrix G ----
    wgrad0_k<<<dim3(64,128), 252, smW0>>>(d0, xp, G, scal);
    wgrad2_k<64,8,4><<<dim3(16,128), 256, sm42>>>(d1, p0, G, OW1, OB1, scal, 2, 42, 42);
    wgrad2_k<64,8,4><<<dim3(16,128), 256, sm21>>>(d2, p1, G, OW2, OB2, scal, 4, 21, 21);
    wgrad2_k<64,8,4><<<dim3(16,128), 256, sm10>>>(d3, p2, G, OW3, OB3, scal, 6, 10, 10);
    copyp3_k<<<(128*1600 + 255)/256, 256>>>(p3, G, scal);

    // ---- K = G1 G2^T + s_fcb^2 ----
    gemm_part_k<<<dim3(4,4,8), dim3(16,16)>>>(G, part);
    reduce_k<<<16,256>>>(part, scal, out);
}